// round 16
// baseline (speedup 1.0000x reference)
#include <cuda_runtime.h>
#include <math.h>
#include <math_constants.h>

// Problem constants
#define T_STEPS 16
#define BATCH   8
#define HH      224
#define WW      224
#define CIN     3
#define CH      32
#define OUT     10
#define NIMG    (T_STEPS * BATCH)      // 128
#define KW      113                     // W/2 + 1
#define HALF    112
#define NF2     55                      // second-level fold pairs (w = 1..55)
#define NF2P    56                      // padded to multiple of 4
#define MAGN    (HH * KW)               // 25312 per image
#define K3_BLOCKS (14 * 14 * BATCH)     // 1568

// -------- device scratch (no allocation allowed) --------
__device__ float2 d_rowspec[(size_t)NIMG * MAGN];   // [img][k][y], ~26 MB
__device__ float  d_mag    [(size_t)NIMG * MAGN];   // [img][y][k], ~13 MB
__device__ int    d_counts[T_STEPS * BATCH * CH];    // spike counts per (t,b,c)
__device__ double d_esum;                            // sum of log1p(mag)
__device__ int    d_ticket;                          // K3 completion ticket

__device__ __forceinline__ int wrap224(int a) { return (a >= WW) ? a - WW : a; }

// per-block twiddle fill: tw[i] = exp(-2*pi*i*i/224), i = 0..223
__device__ __forceinline__ void fill_tw(float2* tw_s, int tid, int nthr) {
    for (int i = tid; i < WW; i += nthr) {
        float a = (float)i * (1.0f / 112.0f);
        tw_s[i] = make_float2(cospif(a), -sinpif(a));
    }
}

// ============================================================
// K1: gray + row rDFT, DOUBLE-folded (w<->224-w, then w<->112-w).
// Also hosts global zero-init (first 32 blocks zero d_counts;
// block 0 zeroes d_esum + d_ticket) — stream-ordered before K2/K3.
// ============================================================
__global__ void __launch_bounds__(128) k_rowdft(const float* __restrict__ x_seq) {
    int blk = blockIdx.x;             // img*14 + yg
    int img = blk / 14;
    int y0  = (blk % 14) * 16;

    __shared__ __align__(16) float g_s[16 * 228];   // [r][w], stride 228
    __shared__ __align__(16) float sE[NF2P * 16], sO[NF2P * 16];
    __shared__ __align__(16) float dE[NF2P * 16], dO[NF2P * 16];
    __shared__ float2 tw_s[WW];
    __shared__ float  g0_s[16], g112_s[16], s56_s[16], d56_s[16];

    int tid = threadIdx.x;

    // global zero-init (replaces k_init; re-runs every graph replay)
    if (blk < 32) d_counts[blk * 128 + tid] = 0;
    if (blk == 0 && tid == 0) { d_esum = 0.0; d_ticket = 0; }

    fill_tw(tw_s, tid, 128);

    // gray: 16 rows x 224 px. 4 pixels = 12 floats = 3 float4.
    {
        const float4* base4 = (const float4*)(x_seq +
            ((size_t)img * HH + y0) * WW * CIN);
        #pragma unroll
        for (int k = 0; k < 7; ++k) {
            int q = tid + k * 128;          // 4-pixel group, 0..895
            float4 a = base4[3 * q];
            float4 b = base4[3 * q + 1];
            float4 c4 = base4[3 * q + 2];
            int r = q / 56;
            int w0 = (q - r * 56) * 4;
            float4 gv;
            gv.x = (a.x + a.y + a.z)  * (1.0f / 3.0f);
            gv.y = (a.w + b.x + b.y)  * (1.0f / 3.0f);
            gv.z = (b.z + b.w + c4.x) * (1.0f / 3.0f);
            gv.w = (c4.y + c4.z + c4.w) * (1.0f / 3.0f);
            *(float4*)&g_s[r * 228 + w0] = gv;
        }
    }
    __syncthreads();

    // double fold
    for (int p = tid; p < NF2P * 16; p += 128) {
        int w = p >> 4, r = p & 15;
        float se = 0.f, so = 0.f, de = 0.f, dq = 0.f;
        if (w < NF2) {
            int wa = w + 1;                           // 1..55
            float a  = g_s[r * 228 + wa];
            float b  = g_s[r * 228 + (224 - wa)];
            float a2 = g_s[r * 228 + (112 - wa)];
            float b2 = g_s[r * 228 + (112 + wa)];
            float s1 = a + b,   d1 = a - b;
            float s2 = a2 + b2, d2 = a2 - b2;
            se = s1 + s2; so = s1 - s2;
            de = d1 - d2; dq = d1 + d2;
        }
        sE[p] = se; sO[p] = so; dE[p] = de; dO[p] = dq;
    }
    if (tid < 16) {
        g0_s[tid]   = g_s[tid * 228];
        g112_s[tid] = g_s[tid * 228 + HALF];
        float a = g_s[tid * 228 + 56], b = g_s[tid * 228 + 168];
        s56_s[tid] = a + b;
        d56_s[tid] = a - b;
    }
    __syncthreads();

    int k = tid;
    if (k >= KW) return;

    int kd = k & 3;
    float c56  = (kd == 0) ? 1.0f : (kd == 2) ? -1.0f : 0.0f;  // cos(pi*k/2)
    float ty56 = (kd == 1) ? -1.0f : (kd == 3) ? 1.0f : 0.0f;  // -sin(pi*k/2)
    float sgn  = (k & 1) ? -1.0f : 1.0f;
    const float* sP = (k & 1) ? sO : sE;
    const float* dP = (k & 1) ? dO : dE;

    float ar[16], ai[16];
    #pragma unroll
    for (int r = 0; r < 16; ++r) {
        ar[r] = g0_s[r] + sgn * g112_s[r] + c56 * s56_s[r];
        ai[r] = ty56 * d56_s[r];
    }

    int km2 = wrap224(k + k);
    int km3 = wrap224(km2 + k);
    int km4 = wrap224(km3 + k);
    int idx = k;

    for (int w = 0; w < NF2P; w += 4) {
        int i0 = idx;
        int i1 = wrap224(i0 + k);
        int i2 = wrap224(i0 + km2);
        int i3 = wrap224(i0 + km3);
        idx = wrap224(idx + km4);
        float2 tq[4] = { tw_s[i0], tw_s[i1], tw_s[i2], tw_s[i3] };
        #pragma unroll
        for (int j = 0; j < 4; ++j) {
            float2 t = tq[j];
            const float4* sp = (const float4*)(sP + (w + j) * 16);
            const float4* dp = (const float4*)(dP + (w + j) * 16);
            #pragma unroll
            for (int q = 0; q < 4; ++q) {
                float4 sv = sp[q], dv = dp[q];
                ar[q*4+0] = fmaf(sv.x, t.x, ar[q*4+0]);
                ar[q*4+1] = fmaf(sv.y, t.x, ar[q*4+1]);
                ar[q*4+2] = fmaf(sv.z, t.x, ar[q*4+2]);
                ar[q*4+3] = fmaf(sv.w, t.x, ar[q*4+3]);
                ai[q*4+0] = fmaf(dv.x, t.y, ai[q*4+0]);
                ai[q*4+1] = fmaf(dv.y, t.y, ai[q*4+1]);
                ai[q*4+2] = fmaf(dv.z, t.y, ai[q*4+2]);
                ai[q*4+3] = fmaf(dv.w, t.y, ai[q*4+3]);
            }
        }
    }

    float4* out = (float4*)(d_rowspec + (size_t)img * MAGN + (size_t)k * HH + y0);
    #pragma unroll
    for (int j = 0; j < 8; ++j)
        out[j] = make_float4(ar[2*j], ai[2*j], ar[2*j+1], ai[2*j+1]);
}

// ============================================================
// K2: column DFT, double-folded in h, folded in m.
// ============================================================
__global__ void __launch_bounds__(128) k_coldft() {
    int blk = blockIdx.x;             // img*15 + kg
    int img = blk / 15;
    int k0  = (blk % 15) * 8;
    int nk  = KW - k0; if (nk > 8) nk = 8;

    __shared__ float2 zraw[8 * 225];                 // [kk][h], stride 225
    __shared__ __align__(16) float2 zsE[NF2P * 8], zsO[NF2P * 8];
    __shared__ __align__(16) float2 zdE[NF2P * 8], zdO[NF2P * 8];
    __shared__ float2 z0_s[8], z112_s[8], zs56_s[8], zd56_s[8];
    __shared__ float2 tw_s[WW];
    __shared__ float  wsum[4];

    int tid = threadIdx.x;
    fill_tw(tw_s, tid, 128);

    for (int p = tid; p < 8 * HH; p += 128) {
        int kk = p / HH, h = p % HH;
        float2 z = make_float2(0.0f, 0.0f);
        if (kk < nk)
            z = d_rowspec[(size_t)img * MAGN + (size_t)(k0 + kk) * HH + h];
        zraw[kk * 225 + h] = z;
    }
    __syncthreads();

    // double fold
    for (int p = tid; p < NF2P * 8; p += 128) {
        int kk = p & 7, w = p >> 3;
        float2 se = make_float2(0.f, 0.f), so = se, de = se, dq = se;
        if (w < NF2) {
            int wa = w + 1;                           // 1..55
            float2 a  = zraw[kk * 225 + wa];
            float2 b  = zraw[kk * 225 + (224 - wa)];
            float2 a2 = zraw[kk * 225 + (112 - wa)];
            float2 b2 = zraw[kk * 225 + (112 + wa)];
            float2 s1 = make_float2(a.x + b.x,   a.y + b.y);
            float2 d1 = make_float2(a.x - b.x,   a.y - b.y);
            float2 s2 = make_float2(a2.x + b2.x, a2.y + b2.y);
            float2 d2 = make_float2(a2.x - b2.x, a2.y - b2.y);
            se = make_float2(s1.x + s2.x, s1.y + s2.y);
            so = make_float2(s1.x - s2.x, s1.y - s2.y);
            de = make_float2(d1.x - d2.x, d1.y - d2.y);
            dq = make_float2(d1.x + d2.x, d1.y + d2.y);
        }
        zsE[w * 8 + kk] = se; zsO[w * 8 + kk] = so;
        zdE[w * 8 + kk] = de; zdO[w * 8 + kk] = dq;
    }
    if (tid < 8) {
        z0_s[tid]   = zraw[tid * 225];
        z112_s[tid] = zraw[tid * 225 + HALF];
        float2 a = zraw[tid * 225 + 56], b = zraw[tid * 225 + 168];
        zs56_s[tid] = make_float2(a.x + b.x, a.y + b.y);
        zd56_s[tid] = make_float2(a.x - b.x, a.y - b.y);
    }
    __syncthreads();

    int m = tid;                           // 0..127; active if <=112
    float esum = 0.0f;

    if (m <= HALF) {
        int md = m & 3;
        float c56  = (md == 0) ? 1.0f : (md == 2) ? -1.0f : 0.0f;
        float ty56 = (md == 1) ? -1.0f : (md == 3) ? 1.0f : 0.0f;
        const float2* zsP = (m & 1) ? zsO : zsE;
        const float2* zdP = (m & 1) ? zdO : zdE;

        float P[8], Q[8], R[8], S[8];
        #pragma unroll
        for (int kk = 0; kk < 8; ++kk) {
            P[kk] = zs56_s[kk].x * c56;
            R[kk] = zs56_s[kk].y * c56;
            Q[kk] = zd56_s[kk].y * ty56;
            S[kk] = zd56_s[kk].x * ty56;
        }

        int m2i = wrap224(m + m);
        int m3i = wrap224(m2i + m);
        int m4i = wrap224(m3i + m);
        int idx = m;

        for (int w = 0; w < NF2P; w += 4) {
            int i0 = idx;
            int i1 = wrap224(i0 + m);
            int i2 = wrap224(i0 + m2i);
            int i3 = wrap224(i0 + m3i);
            idx = wrap224(idx + m4i);
            float2 tq[4] = { tw_s[i0], tw_s[i1], tw_s[i2], tw_s[i3] };
            #pragma unroll
            for (int j = 0; j < 4; ++j) {
                float2 t = tq[j];
                const float4* zsp = (const float4*)(zsP + (w + j) * 8);
                const float4* zdp = (const float4*)(zdP + (w + j) * 8);
                #pragma unroll
                for (int q = 0; q < 4; ++q) {
                    float4 a = zsp[q], b = zdp[q];
                    P[2*q]   = fmaf(a.x, t.x, P[2*q]);
                    R[2*q]   = fmaf(a.y, t.x, R[2*q]);
                    Q[2*q]   = fmaf(b.y, t.y, Q[2*q]);
                    S[2*q]   = fmaf(b.x, t.y, S[2*q]);
                    P[2*q+1] = fmaf(a.z, t.x, P[2*q+1]);
                    R[2*q+1] = fmaf(a.w, t.x, R[2*q+1]);
                    Q[2*q+1] = fmaf(b.w, t.y, Q[2*q+1]);
                    S[2*q+1] = fmaf(b.z, t.y, S[2*q+1]);
                }
            }
        }

        float sgn = (m & 1) ? -1.0f : 1.0f;
        bool have2 = (m >= 1 && m <= 111);       // rows 113..223
        float* mrow1 = d_mag + (size_t)img * MAGN + (size_t)m * KW + k0;
        float* mrow2 = d_mag + (size_t)img * MAGN + (size_t)(WW - m) * KW + k0;

        #pragma unroll
        for (int kk = 0; kk < 8; ++kk) {
            if (kk < nk) {
                float base_r = z0_s[kk].x + sgn * z112_s[kk].x;
                float base_i = z0_s[kk].y + sgn * z112_s[kk].y;
                float ar = base_r + P[kk] - Q[kk];
                float ai = base_i + R[kk] + S[kk];
                float mag1 = __logf(1.0f + sqrtf(fmaf(ar, ar, ai * ai)));
                mrow1[kk] = mag1;
                esum += mag1;
                if (have2) {
                    float br = base_r + P[kk] + Q[kk];
                    float bi = base_i + R[kk] - S[kk];
                    float mag2 = __logf(1.0f + sqrtf(fmaf(br, br, bi * bi)));
                    mrow2[kk] = mag2;
                    esum += mag2;
                }
            }
        }
    }

    #pragma unroll
    for (int o = 16; o; o >>= 1) esum += __shfl_down_sync(0xffffffffu, esum, o);
    if ((tid & 31) == 0) wsum[tid >> 5] = esum;
    __syncthreads();
    if (tid == 0) {
        float tot = wsum[0] + wsum[1] + wsum[2] + wsum[3];
        atomicAdd(&d_esum, (double)tot);
    }
}

// ============================================================
// K3: fused 3x3 conv (4->32 ch) + LIF scan, warp-specialized.
// Last block (by ticket) also performs the K4 finalize:
// head matmul + readout + scalars -> out. (launch count 4->3)
// ============================================================
__global__ void __launch_bounds__(320, 2)
k_convlif(const float* __restrict__ x_seq,
          const float* __restrict__ conv_w,
          const float* __restrict__ conv_b,
          const float* __restrict__ head_w,
          const float* __restrict__ head_b,
          float* __restrict__ out) {
    int b    = blockIdx.y;
    int tile = blockIdx.x;                 // 0..195
    int ty0 = (tile / 14) * 16;
    int tx0 = (tile % 14) * 16;

    int tid = threadIdx.x;
    int c = tid & 31;
    int g = tid >> 5;                      // warp id 0..9

    __shared__ float tile_s[2][4][18][20];   // padded rows (LDS.128-aligned)
    __shared__ float w_s[4][3][3][CH];       // [in][ky][kx][out-ch]
    __shared__ float bias_s[CH];
    __shared__ int   cnt_s[T_STEPS][CH];
    __shared__ int   last_s;
    __shared__ float logits_s[T_STEPS][BATCH][OUT];
    __shared__ long long csum[8];

    for (int p = tid; p < 4 * 9 * CH; p += 320) {
        int cc = p & 31;
        int rest = p >> 5;                 // i*9 + (ky*3+kx)
        int i = rest / 9, kk = rest % 9;
        w_s[i][kk / 3][kk % 3][cc] = conv_w[(kk * 4 + i) * CH + cc];
    }
    if (tid < CH) bias_s[tid] = conv_b[tid];
    if (tid < 256) {
        cnt_s[tid >> 5][c] = 0;
        cnt_s[8 + (tid >> 5)][c] = 0;
    }
    __syncthreads();                       // init barrier (ALL threads)

    const float scale = 113.0f / 224.0f;

    if (g >= 8) {
        // ================= PRODUCER warps (8,9) =================
        int ptid = tid - 256;              // 0..63
        int   syy[6], sxx[6], xoff[6], moff[6];
        float sfrac[6];
        bool  sval[6], sok[6];
        #pragma unroll
        for (int it = 0; it < 6; ++it) {
            int p = ptid + it * 64;
            sval[it] = (p < 324);
            int yy = p / 18, xx = p % 18;
            syy[it] = yy; sxx[it] = xx;
            int gy = ty0 - 1 + yy, gx = tx0 - 1 + xx;
            bool ok = sval[it] && gy >= 0 && gy < HH && gx >= 0 && gx < WW;
            sok[it] = ok;
            int gys = ok ? gy : 0, gxs = ok ? gx : 0;
            float src = fmaf((float)gxs + 0.5f, scale, -0.5f);
            src = fminf(fmaxf(src, 0.0f), 112.0f);
            int i0 = (int)src; if (i0 > 111) i0 = 111;
            sfrac[it] = src - (float)i0;
            xoff[it] = (gys * WW + gxs) * CIN;
            moff[it] = gys * KW + i0;
        }

        float pr[6][3], pa[6], pb[6];
        auto pload = [&](int tt) {
            int img = tt * BATCH + b;
            const float* xb = x_seq + (size_t)img * (HH * WW * CIN);
            const float* mb = d_mag + (size_t)img * MAGN;
            #pragma unroll
            for (int it = 0; it < 6; ++it) {
                float r0 = 0.f, r1 = 0.f, r2 = 0.f, a = 0.f, bb = 0.f;
                if (sok[it]) {
                    const float* px = xb + xoff[it];
                    r0 = px[0]; r1 = px[1]; r2 = px[2];
                    a = mb[moff[it]]; bb = mb[moff[it] + 1];
                }
                pr[it][0] = r0; pr[it][1] = r1; pr[it][2] = r2;
                pa[it] = a; pb[it] = bb;
            }
        };
        auto pstore = [&](int buf) {
            #pragma unroll
            for (int it = 0; it < 6; ++it) {
                if (!sval[it]) continue;
                int yy = syy[it], xx = sxx[it];
                tile_s[buf][0][yy][xx] = pr[it][0];
                tile_s[buf][1][yy][xx] = pr[it][1];
                tile_s[buf][2][yy][xx] = pr[it][2];
                tile_s[buf][3][yy][xx] = fmaf(sfrac[it], pb[it] - pa[it], pa[it]);
            }
        };

        pload(0);
        pstore(0);
        __syncthreads();                   // buffer-0 ready
        for (int t = 0; t < T_STEPS; ++t) {
            if (t + 1 < T_STEPS) {
                pload(t + 1);
                pstore((t + 1) & 1);
            }
            __syncthreads();
        }
    } else {
        // ================= COMPUTE warps (0..7) =================
        float bc = bias_s[c];
        float V[2][16];
        #pragma unroll
        for (int r = 0; r < 2; ++r)
            #pragma unroll
            for (int x = 0; x < 16; ++x) V[r][x] = 0.0f;

        __syncthreads();                   // pairs with producer buffer-0 barrier

        for (int t = 0; t < T_STEPS; ++t) {
            int buf = t & 1;

            #pragma unroll
            for (int r = 0; r < 2; ++r)
                #pragma unroll
                for (int x = 0; x < 16; ++x)
                    V[r][x] = fmaf(0.9f, V[r][x], bc);

            const float (*tp)[18][20] = tile_s[buf];
            #pragma unroll
            for (int i = 0; i < 4; ++i) {
                float w00 = w_s[i][0][0][c], w01 = w_s[i][0][1][c], w02 = w_s[i][0][2][c];
                float w10 = w_s[i][1][0][c], w11 = w_s[i][1][1][c], w12 = w_s[i][1][2][c];
                float w20 = w_s[i][2][0][c], w21 = w_s[i][2][1][c], w22 = w_s[i][2][2][c];
                #pragma unroll
                for (int iy = 0; iy < 4; ++iy) {
                    const float4* rowp = (const float4*)&tp[i][2 * g + iy][0];
                    float v[20];
                    #pragma unroll
                    for (int q = 0; q < 5; ++q) ((float4*)v)[q] = rowp[q];
                    if (iy < 3) {
                        float a0 = (iy == 0) ? w00 : (iy == 1) ? w10 : w20;
                        float a1 = (iy == 0) ? w01 : (iy == 1) ? w11 : w21;
                        float a2 = (iy == 0) ? w02 : (iy == 1) ? w12 : w22;
                        #pragma unroll
                        for (int x = 0; x < 16; ++x)
                            V[0][x] = fmaf(a0, v[x], fmaf(a1, v[x + 1], fmaf(a2, v[x + 2], V[0][x])));
                    }
                    if (iy >= 1) {
                        float a0 = (iy == 1) ? w00 : (iy == 2) ? w10 : w20;
                        float a1 = (iy == 1) ? w01 : (iy == 2) ? w11 : w21;
                        float a2 = (iy == 1) ? w02 : (iy == 2) ? w12 : w22;
                        #pragma unroll
                        for (int x = 0; x < 16; ++x)
                            V[1][x] = fmaf(a0, v[x], fmaf(a1, v[x + 1], fmaf(a2, v[x + 2], V[1][x])));
                    }
                }
            }

            int cnt = 0;
            #pragma unroll
            for (int r = 0; r < 2; ++r)
                #pragma unroll
                for (int x = 0; x < 16; ++x) {
                    if (V[r][x] > 1.0f) { V[r][x] -= 1.0f; ++cnt; }
                }
            atomicAdd(&cnt_s[t][c], cnt);

            __syncthreads();
        }
    }

    // flush spike counts (2 entries per thread, first 256 threads)
    if (tid < 256) {
        int t0 = tid >> 5;
        atomicAdd(&d_counts[(t0 * BATCH + b) * CH + c], cnt_s[t0][c]);
        int t1 = 8 + (tid >> 5);
        atomicAdd(&d_counts[(t1 * BATCH + b) * CH + c], cnt_s[t1][c]);
    }

    // ---- last-block finalize (replaces K4) ----
    __threadfence();
    __syncthreads();
    if (tid == 0) {
        int tkt = atomicAdd(&d_ticket, 1);
        last_s = (tkt == K3_BLOCKS - 1) ? 1 : 0;
    }
    __syncthreads();
    if (!last_s) return;

    // all 1568 blocks' d_counts atomics are visible (fence + ticket acquire)
    if (tid < 256) {
        long long mycnt = 0;
        #pragma unroll
        for (int j = 0; j < 16; ++j)
            mycnt += (long long)d_counts[tid * 16 + j];
        #pragma unroll
        for (int o = 16; o; o >>= 1)
            mycnt += __shfl_down_sync(0xffffffffu, mycnt, o);
        if ((tid & 31) == 0) csum[tid >> 5] = mycnt;
    }

    if (tid < T_STEPS * BATCH) {
        int t = tid >> 3, bb = tid & 7;
        const float inv = 1.0f / (float)(HH * WW);
        float mean[CH];
        #pragma unroll
        for (int cc = 0; cc < CH; ++cc)
            mean[cc] = (float)d_counts[(t * BATCH + bb) * CH + cc] * inv;
        #pragma unroll
        for (int o = 0; o < OUT; ++o) {
            float a = head_b[o];
            #pragma unroll
            for (int cc = 0; cc < CH; ++cc)
                a = fmaf(mean[cc], head_w[cc * OUT + o], a);
            logits_s[t][bb][o] = a;
            out[80 + (t * BATCH + bb) * OUT + o] = a;
        }
    }
    __syncthreads();
    if (tid < BATCH * OUT) {
        int bb = tid / OUT, o = tid % OUT;
        float s = 0.0f;
        #pragma unroll
        for (int t = 0; t < T_STEPS; ++t) s += logits_s[t][bb][o];
        out[tid] = s * (1.0f / (float)T_STEPS);
    }
    if (tid == 0) {
        long long tot = 0;
        #pragma unroll
        for (int i = 0; i < 8; ++i) tot += csum[i];
        out[1360] = (float)((double)tot /
                            ((double)T_STEPS * BATCH * HH * WW * CH));
        out[1361] = (float)(d_esum / ((double)T_STEPS * BATCH * HH * KW));
    }
}

// ============================================================
extern "C" void kernel_launch(void* const* d_in, const int* in_sizes, int n_in,
                              void* d_out, int out_size) {
    const float* x_seq  = (const float*)d_in[0];
    const float* conv_w = (const float*)d_in[1];
    const float* conv_b = (const float*)d_in[2];
    const float* head_w = (const float*)d_in[3];
    const float* head_b = (const float*)d_in[4];
    float* out = (float*)d_out;

    k_rowdft<<<NIMG * 14, 128>>>(x_seq);
    k_coldft<<<NIMG * 15, 128>>>();
    k_convlif<<<dim3(14 * 14, BATCH), 320>>>(x_seq, conv_w, conv_b,
                                             head_w, head_b, out);
}

// round 17
// speedup vs baseline: 1.0681x; 1.0681x over previous
#include <cuda_runtime.h>
#include <math.h>
#include <math_constants.h>

// Problem constants
#define T_STEPS 16
#define BATCH   8
#define HH      224
#define WW      224
#define CIN     3
#define CH      32
#define OUT     10
#define NIMG    (T_STEPS * BATCH)      // 128
#define KW      113                     // W/2 + 1
#define HALF    112
#define NF2     55                      // second-level fold pairs (w = 1..55)
#define NF2P    56                      // padded to multiple of 4
#define MAGN    (HH * KW)               // 25312 per image

// -------- device scratch (no allocation allowed) --------
__device__ float2 d_rowspec[(size_t)NIMG * MAGN];   // [img][k][y], ~26 MB
__device__ float  d_mag    [(size_t)NIMG * MAGN];   // [img][y][k], ~13 MB
__device__ int    d_counts[T_STEPS * BATCH * CH];    // spike counts per (t,b,c)
__device__ double d_esum;                            // sum of log1p(mag)

__device__ __forceinline__ int wrap224(int a) { return (a >= WW) ? a - WW : a; }

// per-block twiddle fill: tw[i] = exp(-2*pi*i*i/224), i = 0..223
__device__ __forceinline__ void fill_tw(float2* tw_s, int tid, int nthr) {
    for (int i = tid; i < WW; i += nthr) {
        float a = (float)i * (1.0f / 112.0f);
        tw_s[i] = make_float2(cospif(a), -sinpif(a));
    }
}

// ============================================================
// K1: gray + row rDFT, DOUBLE-folded.
//  - coalesced staging: 4-row chunks via smem bounce buffer
//    (union'd with fold arrays; zero smem growth)
//  - parity-uniform warp mapping: warps 0,1 even k; 2,3 odd k
//    -> sP/dP LDS.128 broadcasts are single-address per warp
//  - hosts global zero-init (graph-replay-safe)
// ============================================================
__global__ void __launch_bounds__(128) k_rowdft(const float* __restrict__ x_seq) {
    int blk = blockIdx.x;             // img*14 + yg
    int img = blk / 14;
    int y0  = (blk % 14) * 16;

    __shared__ __align__(16) float g_s[16 * 228];   // [r][w], stride 228
    __shared__ __align__(16) float u_s[4 * NF2P * 16]; // raw chunks, then sE/sO/dE/dO
    __shared__ float2 tw_s[WW];
    __shared__ float  g0_s[16], g112_s[16], s56_s[16], d56_s[16];

    float* sEp = u_s;
    float* sOp = u_s + NF2P * 16;
    float* dEp = u_s + 2 * NF2P * 16;
    float* dOp = u_s + 3 * NF2P * 16;

    int tid = threadIdx.x;

    // global zero-init (re-runs every graph replay)
    if (blk < 32) d_counts[blk * 128 + tid] = 0;
    if (blk == 0 && tid == 0) d_esum = 0.0;

    fill_tw(tw_s, tid, 128);

    // ---- coalesced gray staging: 4 chunks of 4 rows ----
    {
        const float4* base4 = (const float4*)(x_seq +
            ((size_t)img * HH + y0) * WW * CIN);
        float4* raw4 = (float4*)u_s;       // 672 float4 = 4 rows RGB
        for (int ch = 0; ch < 4; ++ch) {
            #pragma unroll
            for (int i = tid; i < 672; i += 128)
                raw4[i] = base4[ch * 672 + i];
            __syncthreads();
            #pragma unroll
            for (int p = tid; p < 896; p += 128) {   // 4 rows x 224 px
                int rl = p / 224;
                int w  = p - rl * 224;
                const float* rp = u_s + 3 * p;       // stride-3: conflict-free
                g_s[(ch * 4 + rl) * 228 + w] =
                    (rp[0] + rp[1] + rp[2]) * (1.0f / 3.0f);
            }
            __syncthreads();
        }
    }

    // ---- double fold (overwrites raw buffer) ----
    for (int p = tid; p < NF2P * 16; p += 128) {
        int w = p >> 4, r = p & 15;
        float se = 0.f, so = 0.f, de = 0.f, dq = 0.f;
        if (w < NF2) {
            int wa = w + 1;                           // 1..55
            float a  = g_s[r * 228 + wa];
            float b  = g_s[r * 228 + (224 - wa)];
            float a2 = g_s[r * 228 + (112 - wa)];
            float b2 = g_s[r * 228 + (112 + wa)];
            float s1 = a + b,   d1 = a - b;
            float s2 = a2 + b2, d2 = a2 - b2;
            se = s1 + s2; so = s1 - s2;
            de = d1 - d2; dq = d1 + d2;
        }
        sEp[p] = se; sOp[p] = so; dEp[p] = de; dOp[p] = dq;
    }
    if (tid < 16) {
        g0_s[tid]   = g_s[tid * 228];
        g112_s[tid] = g_s[tid * 228 + HALF];
        float a = g_s[tid * 228 + 56], b = g_s[tid * 228 + 168];
        s56_s[tid] = a + b;
        d56_s[tid] = a - b;
    }
    __syncthreads();

    // ---- parity-uniform k mapping ----
    int k;
    bool act;
    if (tid < 64) { k = tid * 2;            act = (k <= HALF); }   // warps 0,1: even
    else          { k = (tid - 64) * 2 + 1; act = (k <= 111);  }   // warps 2,3: odd
    if (!act) return;

    int kd = k & 3;
    float c56  = (kd == 0) ? 1.0f : (kd == 2) ? -1.0f : 0.0f;  // cos(pi*k/2)
    float ty56 = (kd == 1) ? -1.0f : (kd == 3) ? 1.0f : 0.0f;  // -sin(pi*k/2)
    float sgn  = (k & 1) ? -1.0f : 1.0f;
    const float* sP = (k & 1) ? sOp : sEp;
    const float* dP = (k & 1) ? dOp : dEp;

    float ar[16], ai[16];
    #pragma unroll
    for (int r = 0; r < 16; ++r) {
        ar[r] = g0_s[r] + sgn * g112_s[r] + c56 * s56_s[r];
        ai[r] = ty56 * d56_s[r];
    }

    int km2 = wrap224(k + k);
    int km3 = wrap224(km2 + k);
    int km4 = wrap224(km3 + k);
    int idx = k;

    for (int w = 0; w < NF2P; w += 4) {
        int i0 = idx;
        int i1 = wrap224(i0 + k);
        int i2 = wrap224(i0 + km2);
        int i3 = wrap224(i0 + km3);
        idx = wrap224(idx + km4);
        float2 tq[4] = { tw_s[i0], tw_s[i1], tw_s[i2], tw_s[i3] };
        #pragma unroll
        for (int j = 0; j < 4; ++j) {
            float2 t = tq[j];
            const float4* sp = (const float4*)(sP + (w + j) * 16);
            const float4* dp = (const float4*)(dP + (w + j) * 16);
            #pragma unroll
            for (int q = 0; q < 4; ++q) {
                float4 sv = sp[q], dv = dp[q];
                ar[q*4+0] = fmaf(sv.x, t.x, ar[q*4+0]);
                ar[q*4+1] = fmaf(sv.y, t.x, ar[q*4+1]);
                ar[q*4+2] = fmaf(sv.z, t.x, ar[q*4+2]);
                ar[q*4+3] = fmaf(sv.w, t.x, ar[q*4+3]);
                ai[q*4+0] = fmaf(dv.x, t.y, ai[q*4+0]);
                ai[q*4+1] = fmaf(dv.y, t.y, ai[q*4+1]);
                ai[q*4+2] = fmaf(dv.z, t.y, ai[q*4+2]);
                ai[q*4+3] = fmaf(dv.w, t.y, ai[q*4+3]);
            }
        }
    }

    float4* out = (float4*)(d_rowspec + (size_t)img * MAGN + (size_t)k * HH + y0);
    #pragma unroll
    for (int j = 0; j < 8; ++j)
        out[j] = make_float4(ar[2*j], ai[2*j], ar[2*j+1], ai[2*j+1]);
}

// ============================================================
// K2: column DFT, double-folded in h, folded in m,
// parity-uniform warp mapping on m.
// ============================================================
__global__ void __launch_bounds__(128) k_coldft() {
    int blk = blockIdx.x;             // img*15 + kg
    int img = blk / 15;
    int k0  = (blk % 15) * 8;
    int nk  = KW - k0; if (nk > 8) nk = 8;

    __shared__ float2 zraw[8 * 225];                 // [kk][h], stride 225
    __shared__ __align__(16) float2 zsE[NF2P * 8], zsO[NF2P * 8];
    __shared__ __align__(16) float2 zdE[NF2P * 8], zdO[NF2P * 8];
    __shared__ float2 z0_s[8], z112_s[8], zs56_s[8], zd56_s[8];
    __shared__ float2 tw_s[WW];
    __shared__ float  wsum[4];

    int tid = threadIdx.x;
    fill_tw(tw_s, tid, 128);

    for (int p = tid; p < 8 * HH; p += 128) {
        int kk = p / HH, h = p % HH;
        float2 z = make_float2(0.0f, 0.0f);
        if (kk < nk)
            z = d_rowspec[(size_t)img * MAGN + (size_t)(k0 + kk) * HH + h];
        zraw[kk * 225 + h] = z;
    }
    __syncthreads();

    // double fold
    for (int p = tid; p < NF2P * 8; p += 128) {
        int kk = p & 7, w = p >> 3;
        float2 se = make_float2(0.f, 0.f), so = se, de = se, dq = se;
        if (w < NF2) {
            int wa = w + 1;                           // 1..55
            float2 a  = zraw[kk * 225 + wa];
            float2 b  = zraw[kk * 225 + (224 - wa)];
            float2 a2 = zraw[kk * 225 + (112 - wa)];
            float2 b2 = zraw[kk * 225 + (112 + wa)];
            float2 s1 = make_float2(a.x + b.x,   a.y + b.y);
            float2 d1 = make_float2(a.x - b.x,   a.y - b.y);
            float2 s2 = make_float2(a2.x + b2.x, a2.y + b2.y);
            float2 d2 = make_float2(a2.x - b2.x, a2.y - b2.y);
            se = make_float2(s1.x + s2.x, s1.y + s2.y);
            so = make_float2(s1.x - s2.x, s1.y - s2.y);
            de = make_float2(d1.x - d2.x, d1.y - d2.y);
            dq = make_float2(d1.x + d2.x, d1.y + d2.y);
        }
        zsE[w * 8 + kk] = se; zsO[w * 8 + kk] = so;
        zdE[w * 8 + kk] = de; zdO[w * 8 + kk] = dq;
    }
    if (tid < 8) {
        z0_s[tid]   = zraw[tid * 225];
        z112_s[tid] = zraw[tid * 225 + HALF];
        float2 a = zraw[tid * 225 + 56], b = zraw[tid * 225 + 168];
        zs56_s[tid] = make_float2(a.x + b.x, a.y + b.y);
        zd56_s[tid] = make_float2(a.x - b.x, a.y - b.y);
    }
    __syncthreads();

    // parity-uniform m mapping
    int m;
    bool act;
    if (tid < 64) { m = tid * 2;            act = (m <= HALF); }
    else          { m = (tid - 64) * 2 + 1; act = (m <= 111);  }

    float esum = 0.0f;

    if (act) {
        int md = m & 3;
        float c56  = (md == 0) ? 1.0f : (md == 2) ? -1.0f : 0.0f;
        float ty56 = (md == 1) ? -1.0f : (md == 3) ? 1.0f : 0.0f;
        const float2* zsP = (m & 1) ? zsO : zsE;
        const float2* zdP = (m & 1) ? zdO : zdE;

        float P[8], Q[8], R[8], S[8];
        #pragma unroll
        for (int kk = 0; kk < 8; ++kk) {
            P[kk] = zs56_s[kk].x * c56;
            R[kk] = zs56_s[kk].y * c56;
            Q[kk] = zd56_s[kk].y * ty56;
            S[kk] = zd56_s[kk].x * ty56;
        }

        int m2i = wrap224(m + m);
        int m3i = wrap224(m2i + m);
        int m4i = wrap224(m3i + m);
        int idx = m;

        for (int w = 0; w < NF2P; w += 4) {
            int i0 = idx;
            int i1 = wrap224(i0 + m);
            int i2 = wrap224(i0 + m2i);
            int i3 = wrap224(i0 + m3i);
            idx = wrap224(idx + m4i);
            float2 tq[4] = { tw_s[i0], tw_s[i1], tw_s[i2], tw_s[i3] };
            #pragma unroll
            for (int j = 0; j < 4; ++j) {
                float2 t = tq[j];
                const float4* zsp = (const float4*)(zsP + (w + j) * 8);
                const float4* zdp = (const float4*)(zdP + (w + j) * 8);
                #pragma unroll
                for (int q = 0; q < 4; ++q) {
                    float4 a = zsp[q], b = zdp[q];
                    P[2*q]   = fmaf(a.x, t.x, P[2*q]);
                    R[2*q]   = fmaf(a.y, t.x, R[2*q]);
                    Q[2*q]   = fmaf(b.y, t.y, Q[2*q]);
                    S[2*q]   = fmaf(b.x, t.y, S[2*q]);
                    P[2*q+1] = fmaf(a.z, t.x, P[2*q+1]);
                    R[2*q+1] = fmaf(a.w, t.x, R[2*q+1]);
                    Q[2*q+1] = fmaf(b.w, t.y, Q[2*q+1]);
                    S[2*q+1] = fmaf(b.z, t.y, S[2*q+1]);
                }
            }
        }

        float sgn = (m & 1) ? -1.0f : 1.0f;
        bool have2 = (m >= 1 && m <= 111);       // rows 113..223
        float* mrow1 = d_mag + (size_t)img * MAGN + (size_t)m * KW + k0;
        float* mrow2 = d_mag + (size_t)img * MAGN + (size_t)(WW - m) * KW + k0;

        #pragma unroll
        for (int kk = 0; kk < 8; ++kk) {
            if (kk < nk) {
                float base_r = z0_s[kk].x + sgn * z112_s[kk].x;
                float base_i = z0_s[kk].y + sgn * z112_s[kk].y;
                float ar = base_r + P[kk] - Q[kk];
                float ai = base_i + R[kk] + S[kk];
                float mag1 = __logf(1.0f + sqrtf(fmaf(ar, ar, ai * ai)));
                mrow1[kk] = mag1;
                esum += mag1;
                if (have2) {
                    float br = base_r + P[kk] + Q[kk];
                    float bi = base_i + R[kk] - S[kk];
                    float mag2 = __logf(1.0f + sqrtf(fmaf(br, br, bi * bi)));
                    mrow2[kk] = mag2;
                    esum += mag2;
                }
            }
        }
    }

    #pragma unroll
    for (int o = 16; o; o >>= 1) esum += __shfl_down_sync(0xffffffffu, esum, o);
    if ((tid & 31) == 0) wsum[tid >> 5] = esum;
    __syncthreads();
    if (tid == 0) {
        float tot = wsum[0] + wsum[1] + wsum[2] + wsum[3];
        atomicAdd(&d_esum, (double)tot);
    }
}

// ============================================================
// K3: fused 3x3 conv (4->32 ch) + LIF scan, warp-specialized
// (R12/R15 measured-best form, unchanged).
// ============================================================
__global__ void __launch_bounds__(320, 2)
k_convlif(const float* __restrict__ x_seq,
          const float* __restrict__ conv_w,
          const float* __restrict__ conv_b) {
    int b    = blockIdx.y;
    int tile = blockIdx.x;                 // 0..195
    int ty0 = (tile / 14) * 16;
    int tx0 = (tile % 14) * 16;

    int tid = threadIdx.x;
    int c = tid & 31;
    int g = tid >> 5;                      // warp id 0..9

    __shared__ float tile_s[2][4][18][20];   // padded rows (LDS.128-aligned)
    __shared__ float w_s[4][3][3][CH];       // [in][ky][kx][out-ch]
    __shared__ float bias_s[CH];
    __shared__ int   cnt_s[T_STEPS][CH];

    for (int p = tid; p < 4 * 9 * CH; p += 320) {
        int cc = p & 31;
        int rest = p >> 5;                 // i*9 + (ky*3+kx)
        int i = rest / 9, kk = rest % 9;
        w_s[i][kk / 3][kk % 3][cc] = conv_w[(kk * 4 + i) * CH + cc];
    }
    if (tid < CH) bias_s[tid] = conv_b[tid];
    if (tid < 256) {
        cnt_s[tid >> 5][c] = 0;
        cnt_s[8 + (tid >> 5)][c] = 0;
    }
    __syncthreads();                       // init barrier (ALL threads)

    const float scale = 113.0f / 224.0f;

    if (g >= 8) {
        // ================= PRODUCER warps (8,9) =================
        int ptid = tid - 256;              // 0..63
        int   syy[6], sxx[6], xoff[6], moff[6];
        float sfrac[6];
        bool  sval[6], sok[6];
        #pragma unroll
        for (int it = 0; it < 6; ++it) {
            int p = ptid + it * 64;
            sval[it] = (p < 324);
            int yy = p / 18, xx = p % 18;
            syy[it] = yy; sxx[it] = xx;
            int gy = ty0 - 1 + yy, gx = tx0 - 1 + xx;
            bool ok = sval[it] && gy >= 0 && gy < HH && gx >= 0 && gx < WW;
            sok[it] = ok;
            int gys = ok ? gy : 0, gxs = ok ? gx : 0;
            float src = fmaf((float)gxs + 0.5f, scale, -0.5f);
            src = fminf(fmaxf(src, 0.0f), 112.0f);
            int i0 = (int)src; if (i0 > 111) i0 = 111;
            sfrac[it] = src - (float)i0;
            xoff[it] = (gys * WW + gxs) * CIN;
            moff[it] = gys * KW + i0;
        }

        float pr[6][3], pa[6], pb[6];
        auto pload = [&](int tt) {
            int img = tt * BATCH + b;
            const float* xb = x_seq + (size_t)img * (HH * WW * CIN);
            const float* mb = d_mag + (size_t)img * MAGN;
            #pragma unroll
            for (int it = 0; it < 6; ++it) {
                float r0 = 0.f, r1 = 0.f, r2 = 0.f, a = 0.f, bb = 0.f;
                if (sok[it]) {
                    const float* px = xb + xoff[it];
                    r0 = px[0]; r1 = px[1]; r2 = px[2];
                    a = mb[moff[it]]; bb = mb[moff[it] + 1];
                }
                pr[it][0] = r0; pr[it][1] = r1; pr[it][2] = r2;
                pa[it] = a; pb[it] = bb;
            }
        };
        auto pstore = [&](int buf) {
            #pragma unroll
            for (int it = 0; it < 6; ++it) {
                if (!sval[it]) continue;
                int yy = syy[it], xx = sxx[it];
                tile_s[buf][0][yy][xx] = pr[it][0];
                tile_s[buf][1][yy][xx] = pr[it][1];
                tile_s[buf][2][yy][xx] = pr[it][2];
                tile_s[buf][3][yy][xx] = fmaf(sfrac[it], pb[it] - pa[it], pa[it]);
            }
        };

        pload(0);
        pstore(0);
        __syncthreads();                   // buffer-0 ready
        for (int t = 0; t < T_STEPS; ++t) {
            if (t + 1 < T_STEPS) {
                pload(t + 1);
                pstore((t + 1) & 1);
            }
            __syncthreads();
        }
    } else {
        // ================= COMPUTE warps (0..7) =================
        float bc = bias_s[c];
        float V[2][16];
        #pragma unroll
        for (int r = 0; r < 2; ++r)
            #pragma unroll
            for (int x = 0; x < 16; ++x) V[r][x] = 0.0f;

        __syncthreads();                   // pairs with producer buffer-0 barrier

        for (int t = 0; t < T_STEPS; ++t) {
            int buf = t & 1;

            #pragma unroll
            for (int r = 0; r < 2; ++r)
                #pragma unroll
                for (int x = 0; x < 16; ++x)
                    V[r][x] = fmaf(0.9f, V[r][x], bc);

            const float (*tp)[18][20] = tile_s[buf];
            #pragma unroll
            for (int i = 0; i < 4; ++i) {
                float w00 = w_s[i][0][0][c], w01 = w_s[i][0][1][c], w02 = w_s[i][0][2][c];
                float w10 = w_s[i][1][0][c], w11 = w_s[i][1][1][c], w12 = w_s[i][1][2][c];
                float w20 = w_s[i][2][0][c], w21 = w_s[i][2][1][c], w22 = w_s[i][2][2][c];
                #pragma unroll
                for (int iy = 0; iy < 4; ++iy) {
                    const float4* rowp = (const float4*)&tp[i][2 * g + iy][0];
                    float v[20];
                    #pragma unroll
                    for (int q = 0; q < 5; ++q) ((float4*)v)[q] = rowp[q];
                    if (iy < 3) {
                        float a0 = (iy == 0) ? w00 : (iy == 1) ? w10 : w20;
                        float a1 = (iy == 0) ? w01 : (iy == 1) ? w11 : w21;
                        float a2 = (iy == 0) ? w02 : (iy == 1) ? w12 : w22;
                        #pragma unroll
                        for (int x = 0; x < 16; ++x)
                            V[0][x] = fmaf(a0, v[x], fmaf(a1, v[x + 1], fmaf(a2, v[x + 2], V[0][x])));
                    }
                    if (iy >= 1) {
                        float a0 = (iy == 1) ? w00 : (iy == 2) ? w10 : w20;
                        float a1 = (iy == 1) ? w01 : (iy == 2) ? w11 : w21;
                        float a2 = (iy == 1) ? w02 : (iy == 2) ? w12 : w22;
                        #pragma unroll
                        for (int x = 0; x < 16; ++x)
                            V[1][x] = fmaf(a0, v[x], fmaf(a1, v[x + 1], fmaf(a2, v[x + 2], V[1][x])));
                    }
                }
            }

            int cnt = 0;
            #pragma unroll
            for (int r = 0; r < 2; ++r)
                #pragma unroll
                for (int x = 0; x < 16; ++x) {
                    if (V[r][x] > 1.0f) { V[r][x] -= 1.0f; ++cnt; }
                }
            atomicAdd(&cnt_s[t][c], cnt);

            __syncthreads();
        }
    }

    if (tid < 256) {
        int t0 = tid >> 5;
        atomicAdd(&d_counts[(t0 * BATCH + b) * CH + c], cnt_s[t0][c]);
        int t1 = 8 + (tid >> 5);
        atomicAdd(&d_counts[(t1 * BATCH + b) * CH + c], cnt_s[t1][c]);
    }
}

// ============================================================
// K4: head matmul + readout + scalars (parallel count reduce).
// ============================================================
__global__ void k_final(const float* __restrict__ head_w,
                        const float* __restrict__ head_b,
                        float* __restrict__ out) {
    __shared__ float logits_s[T_STEPS][BATCH][OUT];
    __shared__ long long csum[8];
    int tid = threadIdx.x;

    long long mycnt = 0;
    #pragma unroll
    for (int j = 0; j < 16; ++j)
        mycnt += (long long)d_counts[tid * 16 + j];
    #pragma unroll
    for (int o = 16; o; o >>= 1)
        mycnt += __shfl_down_sync(0xffffffffu, mycnt, o);
    if ((tid & 31) == 0) csum[tid >> 5] = mycnt;

    if (tid < T_STEPS * BATCH) {
        int t = tid >> 3, b = tid & 7;
        const float inv = 1.0f / (float)(HH * WW);
        float mean[CH];
        #pragma unroll
        for (int c = 0; c < CH; ++c)
            mean[c] = (float)d_counts[(t * BATCH + b) * CH + c] * inv;
        #pragma unroll
        for (int o = 0; o < OUT; ++o) {
            float a = head_b[o];
            #pragma unroll
            for (int c = 0; c < CH; ++c)
                a = fmaf(mean[c], head_w[c * OUT + o], a);
            logits_s[t][b][o] = a;
            out[80 + (t * BATCH + b) * OUT + o] = a;
        }
    }
    __syncthreads();
    if (tid < BATCH * OUT) {
        int b = tid / OUT, o = tid % OUT;
        float s = 0.0f;
        #pragma unroll
        for (int t = 0; t < T_STEPS; ++t) s += logits_s[t][b][o];
        out[tid] = s * (1.0f / (float)T_STEPS);
    }
    if (tid == 0) {
        long long tot = 0;
        #pragma unroll
        for (int i = 0; i < 8; ++i) tot += csum[i];
        out[1360] = (float)((double)tot /
                            ((double)T_STEPS * BATCH * HH * WW * CH));
        out[1361] = (float)(d_esum / ((double)T_STEPS * BATCH * HH * KW));
    }
}

// ============================================================
extern "C" void kernel_launch(void* const* d_in, const int* in_sizes, int n_in,
                              void* d_out, int out_size) {
    const float* x_seq  = (const float*)d_in[0];
    const float* conv_w = (const float*)d_in[1];
    const float* conv_b = (const float*)d_in[2];
    const float* head_w = (const float*)d_in[3];
    const float* head_b = (const float*)d_in[4];
    float* out = (float*)d_out;

    k_rowdft<<<NIMG * 14, 128>>>(x_seq);
    k_coldft<<<NIMG * 15, 128>>>();
    k_convlif<<<dim3(14 * 14, BATCH), 320>>>(x_seq, conv_w, conv_b);
    k_final<<<1, 256>>>(head_w, head_b, out);
}